// round 1
// baseline (speedup 1.0000x reference)
#include <cuda_runtime.h>

#define B_  2
#define C_  256
#define H_  128
#define W_  128
#define HW_ (H_ * W_)
#define NH  32
#define NW  32

// Static scratch (no runtime allocation allowed).
__device__ float g_Wt[3][C_ * C_];                       // transposed weights [k][m]
__device__ float g_QKV[3][(size_t)B_ * C_ * HW_];        // Q, K, V in [B][C][H][W]

// ---------------------------------------------------------------------------
// Kernel 0: transpose the three 256x256 projection weights: Wt[k][m] = W[m][k]
// ---------------------------------------------------------------------------
__global__ void __launch_bounds__(256) transpose_w_kernel(
    const float* __restrict__ qw, const float* __restrict__ kw,
    const float* __restrict__ vw) {
  int idx = blockIdx.x * 256 + threadIdx.x;   // 0 .. 3*65536-1
  int p = idx >> 16;
  int r = idx & 0xFFFF;
  int m = r >> 8;
  int k = r & 255;
  const float* w = (p == 0) ? qw : (p == 1) ? kw : vw;
  g_Wt[p][k * C_ + m] = w[m * C_ + k];
}

// ---------------------------------------------------------------------------
// Kernel 1: fused projection GEMMs.
// Out[p][b][m][n] = sum_k Wt[p][k][m] * X[b][k][n] + bias[p][m]
//   p=0: X=blue (Q), p=1/2: X=white (K/V).  M=256, N=16384, K=256.
// 128x128 block tile, BK=16, 8x8 per thread (4+4 split), prefetched.
// ---------------------------------------------------------------------------
__global__ void __launch_bounds__(256) gemm_proj_kernel(
    const float* __restrict__ blue, const float* __restrict__ white,
    const float* __restrict__ qb, const float* __restrict__ kb,
    const float* __restrict__ vb) {
  const int z = blockIdx.z;       // 0..5
  const int p = z % 3;
  const int b = z / 3;

  const float* __restrict__ X    = ((p == 0) ? blue : white) + (size_t)b * C_ * HW_;
  const float* __restrict__ bias = (p == 0) ? qb : (p == 1) ? kb : vb;
  const float* __restrict__ Wt   = g_Wt[p];
  float* __restrict__ Out        = g_QKV[p] + (size_t)b * C_ * HW_;

  const int n0 = blockIdx.x * 128;
  const int m0 = blockIdx.y * 128;

  __shared__ float Ws[16][128];
  __shared__ float Xs[16][128];

  const int tid = threadIdx.x;
  const int tm  = tid >> 4;       // 0..15
  const int tn  = tid & 15;       // 0..15

  // gmem staging: 16x128 floats per tile = 512 float4 slots; thread takes
  // slot tid (k-rows 0..7) and slot tid+256 (k-rows 8..15).
  const int kr0 = tid >> 5;       // 0..7
  const int kr1 = kr0 + 8;        // 8..15
  const int c4  = (tid & 31) << 2;

  const float* Ap0 = Wt + kr0 * C_ + m0 + c4;
  const float* Ap1 = Wt + kr1 * C_ + m0 + c4;
  const float* Bp0 = X + (size_t)kr0 * HW_ + n0 + c4;
  const float* Bp1 = X + (size_t)kr1 * HW_ + n0 + c4;

  float acc[8][8];
#pragma unroll
  for (int i = 0; i < 8; i++)
#pragma unroll
    for (int jj = 0; jj < 8; jj++) acc[i][jj] = 0.f;

  float4 ra0 = *(const float4*)Ap0;
  float4 ra1 = *(const float4*)Ap1;
  float4 rb0 = *(const float4*)Bp0;
  float4 rb1 = *(const float4*)Bp1;

  for (int t = 0; t < 16; ++t) {
    *(float4*)&Ws[kr0][c4] = ra0;
    *(float4*)&Ws[kr1][c4] = ra1;
    *(float4*)&Xs[kr0][c4] = rb0;
    *(float4*)&Xs[kr1][c4] = rb1;
    __syncthreads();

    if (t < 15) {   // prefetch next K-tile while computing this one
      Ap0 += 16 * C_;  Ap1 += 16 * C_;
      Bp0 += (size_t)16 * HW_;  Bp1 += (size_t)16 * HW_;
      ra0 = *(const float4*)Ap0;
      ra1 = *(const float4*)Ap1;
      rb0 = *(const float4*)Bp0;
      rb1 = *(const float4*)Bp1;
    }

#pragma unroll
    for (int kk = 0; kk < 16; ++kk) {
      float4 a0 = *(const float4*)&Ws[kk][tm << 2];
      float4 a1 = *(const float4*)&Ws[kk][64 + (tm << 2)];
      float4 b0 = *(const float4*)&Xs[kk][tn << 2];
      float4 b1 = *(const float4*)&Xs[kk][64 + (tn << 2)];
      float av[8] = {a0.x, a0.y, a0.z, a0.w, a1.x, a1.y, a1.z, a1.w};
      float bv[8] = {b0.x, b0.y, b0.z, b0.w, b1.x, b1.y, b1.z, b1.w};
#pragma unroll
      for (int i = 0; i < 8; i++)
#pragma unroll
        for (int jj = 0; jj < 8; jj++)
          acc[i][jj] = fmaf(av[i], bv[jj], acc[i][jj]);
    }
    __syncthreads();
  }

#pragma unroll
  for (int i = 0; i < 8; i++) {
    int m = m0 + ((i < 4) ? (tm * 4 + i) : (64 + tm * 4 + (i - 4)));
    float bi = bias[m];
    float4 o0 = make_float4(acc[i][0] + bi, acc[i][1] + bi,
                            acc[i][2] + bi, acc[i][3] + bi);
    float4 o1 = make_float4(acc[i][4] + bi, acc[i][5] + bi,
                            acc[i][6] + bi, acc[i][7] + bi);
    *(float4*)&Out[(size_t)m * HW_ + n0 + (tn << 2)]      = o0;
    *(float4*)&Out[(size_t)m * HW_ + n0 + 64 + (tn << 2)] = o1;
  }
}

// ---------------------------------------------------------------------------
// Kernel 2: per-channel 3x3-neighbor token attention.
// One thread per (b, i, j, c): q token (4x4), dot with 9 neighbor K tokens,
// masked softmax over valid neighbors, weighted sum of V tokens.
// threadIdx.x = j so warp loads are contiguous rows (coalesced float4).
// ---------------------------------------------------------------------------
__global__ void __launch_bounds__(128) attn_kernel(float* __restrict__ out) {
  const int j  = threadIdx.x;                 // 0..31 (tile col)
  const int i  = blockIdx.x;                  // 0..31 (tile row)
  const int c  = blockIdx.y * 4 + threadIdx.y;
  const int b  = blockIdx.z;

  const size_t base = ((size_t)b * C_ + c) * HW_;
  const float* __restrict__ Qp = g_QKV[0] + base;
  const float* __restrict__ Kp = g_QKV[1] + base;
  const float* __restrict__ Vp = g_QKV[2] + base;

  const int y0 = i * 4;
  const int x0 = j * 4;

  float4 q0 = *(const float4*)(Qp + (y0 + 0) * W_ + x0);
  float4 q1 = *(const float4*)(Qp + (y0 + 1) * W_ + x0);
  float4 q2 = *(const float4*)(Qp + (y0 + 2) * W_ + x0);
  float4 q3 = *(const float4*)(Qp + (y0 + 3) * W_ + x0);

  float lg[9];
  float mx = -1e30f;
#pragma unroll
  for (int n = 0; n < 9; n++) {
    const int ii = i + n / 3 - 1;
    const int jj = j + n % 3 - 1;
    float d = -1e30f;
    if ((unsigned)ii < (unsigned)NH && (unsigned)jj < (unsigned)NW) {
      const float* kp = Kp + (ii * 4) * W_ + jj * 4;
      float4 k0 = *(const float4*)(kp);
      float4 k1 = *(const float4*)(kp + W_);
      float4 k2 = *(const float4*)(kp + 2 * W_);
      float4 k3 = *(const float4*)(kp + 3 * W_);
      d  = q0.x * k0.x + q0.y * k0.y + q0.z * k0.z + q0.w * k0.w;
      d += q1.x * k1.x + q1.y * k1.y + q1.z * k1.z + q1.w * k1.w;
      d += q2.x * k2.x + q2.y * k2.y + q2.z * k2.z + q2.w * k2.w;
      d += q3.x * k3.x + q3.y * k3.y + q3.z * k3.z + q3.w * k3.w;
      d *= 0.25f;   // SCALE = (256/16)^-0.5
    }
    lg[n] = d;
    mx = fmaxf(mx, d);
  }

  float wn[9];
  float wsum = 0.f;
#pragma unroll
  for (int n = 0; n < 9; n++) {
    float e = __expf(lg[n] - mx);   // invalid: exp(-1e30-mx) underflows to 0
    wn[n] = e;
    wsum += e;
  }
  const float inv = 1.f / wsum;

  float4 o0 = {0, 0, 0, 0}, o1 = {0, 0, 0, 0}, o2 = {0, 0, 0, 0}, o3 = {0, 0, 0, 0};
#pragma unroll
  for (int n = 0; n < 9; n++) {
    const int ii = i + n / 3 - 1;
    const int jj = j + n % 3 - 1;
    if ((unsigned)ii < (unsigned)NH && (unsigned)jj < (unsigned)NW) {
      const float a = wn[n] * inv;
      const float* vp = Vp + (ii * 4) * W_ + jj * 4;
      float4 v0 = *(const float4*)(vp);
      float4 v1 = *(const float4*)(vp + W_);
      float4 v2 = *(const float4*)(vp + 2 * W_);
      float4 v3 = *(const float4*)(vp + 3 * W_);
      o0.x = fmaf(a, v0.x, o0.x); o0.y = fmaf(a, v0.y, o0.y);
      o0.z = fmaf(a, v0.z, o0.z); o0.w = fmaf(a, v0.w, o0.w);
      o1.x = fmaf(a, v1.x, o1.x); o1.y = fmaf(a, v1.y, o1.y);
      o1.z = fmaf(a, v1.z, o1.z); o1.w = fmaf(a, v1.w, o1.w);
      o2.x = fmaf(a, v2.x, o2.x); o2.y = fmaf(a, v2.y, o2.y);
      o2.z = fmaf(a, v2.z, o2.z); o2.w = fmaf(a, v2.w, o2.w);
      o3.x = fmaf(a, v3.x, o3.x); o3.y = fmaf(a, v3.y, o3.y);
      o3.z = fmaf(a, v3.z, o3.z); o3.w = fmaf(a, v3.w, o3.w);
    }
  }

  float* op = out + base + (size_t)y0 * W_ + x0;
  *(float4*)(op)          = o0;
  *(float4*)(op + W_)     = o1;
  *(float4*)(op + 2 * W_) = o2;
  *(float4*)(op + 3 * W_) = o3;
}

// ---------------------------------------------------------------------------
extern "C" void kernel_launch(void* const* d_in, const int* in_sizes, int n_in,
                              void* d_out, int out_size) {
  const float* blue  = (const float*)d_in[0];
  const float* white = (const float*)d_in[1];
  const float* qw    = (const float*)d_in[2];
  const float* qb    = (const float*)d_in[3];
  const float* kw    = (const float*)d_in[4];
  const float* kb    = (const float*)d_in[5];
  const float* vw    = (const float*)d_in[6];
  const float* vb    = (const float*)d_in[7];

  transpose_w_kernel<<<(3 * C_ * C_) / 256, 256>>>(qw, kw, vw);
  gemm_proj_kernel<<<dim3(HW_ / 128, C_ / 128, 3 * B_), 256>>>(blue, white, qb, kb, vb);
  attn_kernel<<<dim3(NH, C_ / 4, B_), dim3(NW, 4)>>>((float*)d_out);
}

// round 3
// speedup vs baseline: 1.6828x; 1.6828x over previous
#include <cuda_runtime.h>
#include <cuda_bf16.h>
#include <cstdint>

#define B_  2
#define C_  256
#define H_  128
#define W_  128
#define HW_ (H_ * W_)
#define NH  32
#define NW  32

// ---------------------------------------------------------------------------
// Static scratch (no runtime allocation allowed).
// ---------------------------------------------------------------------------
__device__ __align__(256) __nv_bfloat16 g_Wh[3][C_ * C_];          // weight hi, [O][K] K-major
__device__ __align__(256) __nv_bfloat16 g_Wl[3][C_ * C_];          // weight lo
__device__ __align__(256) __nv_bfloat16 g_Xh[4][(size_t)HW_ * C_]; // X^T hi, [hw][c]
__device__ __align__(256) __nv_bfloat16 g_Xl[4][(size_t)HW_ * C_]; // X^T lo
__device__ float g_QKV[3][(size_t)B_ * C_ * HW_];                  // Q,K,V fp32 [b][c][hw]

// ---------------------------------------------------------------------------
// Helpers
// ---------------------------------------------------------------------------
__device__ __forceinline__ uint32_t smem_u32(const void* p) {
  uint32_t a;
  asm("{ .reg .u64 t; cvta.to.shared.u64 t, %1; cvt.u32.u64 %0, t; }" : "=r"(a) : "l"(p));
  return a;
}

#define CP_ASYNC16(s, g) \
  asm volatile("cp.async.cg.shared.global [%0], [%1], 16;" :: "r"(s), "l"(g))
#define CP_COMMIT() asm volatile("cp.async.commit_group;" ::: "memory")
#define CP_WAIT0()  asm volatile("cp.async.wait_group 0;" ::: "memory")
#define CP_WAIT1()  asm volatile("cp.async.wait_group 1;" ::: "memory")

__device__ __forceinline__ void ldsm_x4(uint32_t* r, uint32_t addr) {
  asm volatile("ldmatrix.sync.aligned.m8n8.x4.shared.b16 {%0,%1,%2,%3}, [%4];"
               : "=r"(r[0]), "=r"(r[1]), "=r"(r[2]), "=r"(r[3]) : "r"(addr));
}

__device__ __forceinline__ void mma_bf16(float* c, const uint32_t* a, const uint32_t* b) {
  asm volatile(
      "mma.sync.aligned.m16n8k16.row.col.f32.bf16.bf16.f32 "
      "{%0,%1,%2,%3}, {%4,%5,%6,%7}, {%8,%9}, {%0,%1,%2,%3};"
      : "+f"(c[0]), "+f"(c[1]), "+f"(c[2]), "+f"(c[3])
      : "r"(a[0]), "r"(a[1]), "r"(a[2]), "r"(a[3]), "r"(b[0]), "r"(b[1]));
}

// smem tile: 128 rows x 32 bf16 (64B rows, 4 x 16B chunks, XOR swizzle)
__device__ __forceinline__ uint32_t soff(int r, int c) {
  return (uint32_t)(r * 64 + ((c ^ ((r >> 1) & 3)) << 4));
}

// ---------------------------------------------------------------------------
// Kernel 0a: split weights into bf16 hi/lo (already K-major, no transpose).
// ---------------------------------------------------------------------------
__global__ void __launch_bounds__(256) convert_w_kernel(
    const float* __restrict__ qw, const float* __restrict__ kw,
    const float* __restrict__ vw) {
  int idx = blockIdx.x * 256 + threadIdx.x;
  int p = idx >> 16;
  int r = idx & 0xFFFF;
  const float* w = (p == 0) ? qw : (p == 1) ? kw : vw;
  float x = w[r];
  __nv_bfloat16 hi = __float2bfloat16(x);
  g_Wh[p][r] = hi;
  g_Wl[p][r] = __float2bfloat16(x - __bfloat162float(hi));
}

// ---------------------------------------------------------------------------
// Kernel 0b: transpose X [c][hw] -> [hw][c] and split into bf16 hi/lo.
// ---------------------------------------------------------------------------
__global__ void __launch_bounds__(256) convert_x_kernel(
    const float* __restrict__ blue, const float* __restrict__ white) {
  __shared__ float t[32][33];
  const int hw0 = blockIdx.x * 32;
  const int c0 = blockIdx.y * 32;
  const int slab = blockIdx.z;
  const float* src = (slab < 2) ? blue + (size_t)slab * C_ * HW_
                                : white + (size_t)(slab - 2) * C_ * HW_;
  const int tx = threadIdx.x, ty = threadIdx.y;
#pragma unroll
  for (int it = 0; it < 4; it++) {
    int c = it * 8 + ty;
    t[c][tx] = src[(size_t)(c0 + c) * HW_ + hw0 + tx];
  }
  __syncthreads();
  const int tid = ty * 32 + tx;
  const int cp = tid & 15;
  const int hy = tid >> 4;
  __nv_bfloat16* Xh = g_Xh[slab];
  __nv_bfloat16* Xl = g_Xl[slab];
#pragma unroll
  for (int it = 0; it < 2; it++) {
    int hw = it * 16 + hy;
    float a = t[cp * 2][hw];
    float b = t[cp * 2 + 1][hw];
    __nv_bfloat16 ha = __float2bfloat16(a), hb = __float2bfloat16(b);
    __nv_bfloat16 la = __float2bfloat16(a - __bfloat162float(ha));
    __nv_bfloat16 lb = __float2bfloat16(b - __bfloat162float(hb));
    size_t o = (size_t)(hw0 + hw) * C_ + c0 + cp * 2;
    __nv_bfloat162 vh; vh.x = ha; vh.y = hb;
    __nv_bfloat162 vl; vl.x = la; vl.y = lb;
    *(__nv_bfloat162*)(Xh + o) = vh;
    *(__nv_bfloat162*)(Xl + o) = vl;
  }
}

// ---------------------------------------------------------------------------
// Kernel 1: bf16 hi/lo 3-pass GEMM via mma.sync (HMMA).
// Out[p][b][m][n] = sum_k W[m][k] * X^T[n][k] + bias[m]
// CTA: 128(m) x 128(n), BK=32, 8 warps (2x4), warp 64x32, cp.async pipeline.
// ---------------------------------------------------------------------------
__global__ void __launch_bounds__(256, 1) gemm_mma_kernel(
    const float* __restrict__ qb, const float* __restrict__ kb,
    const float* __restrict__ vb) {
  extern __shared__ char sm[];
  const uint32_t sbase = smem_u32(sm);

  const int tid = threadIdx.x;
  const int lane = tid & 31;
  const int wid = tid >> 5;
  const int wm = wid >> 2;          // 0..1
  const int wn = wid & 3;           // 0..3

  const int z = blockIdx.z;         // 0..5
  const int p = z >> 1;
  const int b = z & 1;
  const int m0 = blockIdx.y * 128;
  const int n0 = blockIdx.x * 128;
  const int slab = (p == 0) ? b : 2 + b;

  const __nv_bfloat16* __restrict__ gAh = g_Wh[p] + m0 * C_;
  const __nv_bfloat16* __restrict__ gAl = g_Wl[p] + m0 * C_;
  const __nv_bfloat16* __restrict__ gBh = g_Xh[slab] + (size_t)n0 * C_;
  const __nv_bfloat16* __restrict__ gBl = g_Xl[slab] + (size_t)n0 * C_;

  // buffer layout: [Ahi 8K][Alo 8K][Bhi 8K][Blo 8K], x2 buffers
  const int stg_r = tid >> 2;           // rows this thread stages (and +64)
  const int stg_c = tid & 3;

  float acc[4][4][4];
#pragma unroll
  for (int mt = 0; mt < 4; mt++)
#pragma unroll
    for (int nt = 0; nt < 4; nt++)
#pragma unroll
      for (int e = 0; e < 4; e++) acc[mt][nt][e] = 0.f;

#define ISSUE_STAGE(ks, buf)                                                     \
  {                                                                              \
    const int k0 = (ks) * 32;                                                    \
    _Pragma("unroll")                                                            \
    for (int it = 0; it < 2; it++) {                                             \
      int r = stg_r + it * 64;                                                   \
      uint32_t so = sbase + (buf) * 32768 + soff(r, stg_c);                      \
      const __nv_bfloat16* ga = gAh + r * C_ + k0 + stg_c * 8;                   \
      const __nv_bfloat16* gb = gBh + (size_t)r * C_ + k0 + stg_c * 8;           \
      CP_ASYNC16(so,         ga);                                                \
      CP_ASYNC16(so + 8192,  gAl + r * C_ + k0 + stg_c * 8);                     \
      CP_ASYNC16(so + 16384, gb);                                                \
      CP_ASYNC16(so + 24576, gBl + (size_t)r * C_ + k0 + stg_c * 8);             \
    }                                                                            \
    CP_COMMIT();                                                                 \
  }

  ISSUE_STAGE(0, 0);

  for (int ks = 0; ks < 8; ks++) {
    const int buf = ks & 1;
    if (ks + 1 < 8) {
      ISSUE_STAGE(ks + 1, buf ^ 1);
      CP_WAIT1();
    } else {
      CP_WAIT0();
    }
    __syncthreads();

    const uint32_t Ab = sbase + buf * 32768;
    const uint32_t Bb = Ab + 16384;

#pragma unroll
    for (int kc = 0; kc < 2; kc++) {
      uint32_t ah[4][4], al[4][4], bh[2][4], bl[2][4];
      const int arow = wm * 64 + (lane & 15);
      const int achunk = kc * 2 + (lane >> 4);
#pragma unroll
      for (int mt = 0; mt < 4; mt++) {
        int rr = arow + mt * 16;
        uint32_t ad = Ab + soff(rr, achunk);
        ldsm_x4(ah[mt], ad);
        ldsm_x4(al[mt], ad + 8192);
      }
      const int nrow = wn * 32 + ((lane >> 4) << 3) + (lane & 7);
      const int bchunk = kc * 2 + ((lane >> 3) & 1);
#pragma unroll
      for (int bt = 0; bt < 2; bt++) {
        int rr = nrow + bt * 16;
        uint32_t bd = Bb + soff(rr, bchunk);
        ldsm_x4(bh[bt], bd);
        ldsm_x4(bl[bt], bd + 8192);
      }
#pragma unroll
      for (int mt = 0; mt < 4; mt++) {
#pragma unroll
        for (int nt = 0; nt < 4; nt++) {
          const uint32_t* bhp = &bh[nt >> 1][(nt & 1) * 2];
          const uint32_t* blp = &bl[nt >> 1][(nt & 1) * 2];
          mma_bf16(acc[mt][nt], ah[mt], bhp);
          mma_bf16(acc[mt][nt], al[mt], bhp);
          mma_bf16(acc[mt][nt], ah[mt], blp);
        }
      }
    }
    __syncthreads();
  }

  // ---- epilogue: bias + direct STG (float2 per fragment row) ----
  const float* __restrict__ biasp = (p == 0) ? qb : (p == 1) ? kb : vb;
  float* __restrict__ Out = g_QKV[p] + (size_t)b * C_ * HW_;
  const int mrow_base = m0 + wm * 64 + (lane >> 2);
  const int ncol_base = n0 + wn * 32 + (lane & 3) * 2;

#pragma unroll
  for (int mt = 0; mt < 4; mt++) {
    int mr = mrow_base + mt * 16;
    float bi0 = __ldg(biasp + mr);
    float bi1 = __ldg(biasp + mr + 8);
#pragma unroll
    for (int nt = 0; nt < 4; nt++) {
      int nc = ncol_base + nt * 8;
      float2 v0 = make_float2(acc[mt][nt][0] + bi0, acc[mt][nt][1] + bi0);
      float2 v1 = make_float2(acc[mt][nt][2] + bi1, acc[mt][nt][3] + bi1);
      *(float2*)(Out + (size_t)mr * HW_ + nc)       = v0;
      *(float2*)(Out + (size_t)(mr + 8) * HW_ + nc) = v1;
    }
  }
}

// ---------------------------------------------------------------------------
// Kernel 2: per-channel 3x3-neighbor token attention (unchanged).
// ---------------------------------------------------------------------------
__global__ void __launch_bounds__(128) attn_kernel(float* __restrict__ out) {
  const int j = threadIdx.x;
  const int i = blockIdx.x;
  const int c = blockIdx.y * 4 + threadIdx.y;
  const int b = blockIdx.z;

  const size_t base = ((size_t)b * C_ + c) * HW_;
  const float* __restrict__ Qp = g_QKV[0] + base;
  const float* __restrict__ Kp = g_QKV[1] + base;
  const float* __restrict__ Vp = g_QKV[2] + base;

  const int y0 = i * 4;
  const int x0 = j * 4;

  float4 q0 = *(const float4*)(Qp + (y0 + 0) * W_ + x0);
  float4 q1 = *(const float4*)(Qp + (y0 + 1) * W_ + x0);
  float4 q2 = *(const float4*)(Qp + (y0 + 2) * W_ + x0);
  float4 q3 = *(const float4*)(Qp + (y0 + 3) * W_ + x0);

  float lg[9];
  float mx = -1e30f;
#pragma unroll
  for (int n = 0; n < 9; n++) {
    const int ii = i + n / 3 - 1;
    const int jj = j + n % 3 - 1;
    float d = -1e30f;
    if ((unsigned)ii < (unsigned)NH && (unsigned)jj < (unsigned)NW) {
      const float* kp = Kp + (ii * 4) * W_ + jj * 4;
      float4 k0 = *(const float4*)(kp);
      float4 k1 = *(const float4*)(kp + W_);
      float4 k2 = *(const float4*)(kp + 2 * W_);
      float4 k3 = *(const float4*)(kp + 3 * W_);
      d  = q0.x * k0.x + q0.y * k0.y + q0.z * k0.z + q0.w * k0.w;
      d += q1.x * k1.x + q1.y * k1.y + q1.z * k1.z + q1.w * k1.w;
      d += q2.x * k2.x + q2.y * k2.y + q2.z * k2.z + q2.w * k2.w;
      d += q3.x * k3.x + q3.y * k3.y + q3.z * k3.z + q3.w * k3.w;
      d *= 0.25f;
    }
    lg[n] = d;
    mx = fmaxf(mx, d);
  }

  float wn[9];
  float wsum = 0.f;
#pragma unroll
  for (int n = 0; n < 9; n++) {
    float e = __expf(lg[n] - mx);
    wn[n] = e;
    wsum += e;
  }
  const float inv = 1.f / wsum;

  float4 o0 = {0, 0, 0, 0}, o1 = {0, 0, 0, 0}, o2 = {0, 0, 0, 0}, o3 = {0, 0, 0, 0};
#pragma unroll
  for (int n = 0; n < 9; n++) {
    const int ii = i + n / 3 - 1;
    const int jj = j + n % 3 - 1;
    if ((unsigned)ii < (unsigned)NH && (unsigned)jj < (unsigned)NW) {
      const float a = wn[n] * inv;
      const float* vp = Vp + (ii * 4) * W_ + jj * 4;
      float4 v0 = *(const float4*)(vp);
      float4 v1 = *(const float4*)(vp + W_);
      float4 v2 = *(const float4*)(vp + 2 * W_);
      float4 v3 = *(const float4*)(vp + 3 * W_);
      o0.x = fmaf(a, v0.x, o0.x); o0.y = fmaf(a, v0.y, o0.y);
      o0.z = fmaf(a, v0.z, o0.z); o0.w = fmaf(a, v0.w, o0.w);
      o1.x = fmaf(a, v1.x, o1.x); o1.y = fmaf(a, v1.y, o1.y);
      o1.z = fmaf(a, v1.z, o1.z); o1.w = fmaf(a, v1.w, o1.w);
      o2.x = fmaf(a, v2.x, o2.x); o2.y = fmaf(a, v2.y, o2.y);
      o2.z = fmaf(a, v2.z, o2.z); o2.w = fmaf(a, v2.w, o2.w);
      o3.x = fmaf(a, v3.x, o3.x); o3.y = fmaf(a, v3.y, o3.y);
      o3.z = fmaf(a, v3.z, o3.z); o3.w = fmaf(a, v3.w, o3.w);
    }
  }

  float* op = out + base + (size_t)y0 * W_ + x0;
  *(float4*)(op)          = o0;
  *(float4*)(op + W_)     = o1;
  *(float4*)(op + 2 * W_) = o2;
  *(float4*)(op + 3 * W_) = o3;
}

// ---------------------------------------------------------------------------
extern "C" void kernel_launch(void* const* d_in, const int* in_sizes, int n_in,
                              void* d_out, int out_size) {
  const float* blue  = (const float*)d_in[0];
  const float* white = (const float*)d_in[1];
  const float* qw    = (const float*)d_in[2];
  const float* qb    = (const float*)d_in[3];
  const float* kw    = (const float*)d_in[4];
  const float* kb    = (const float*)d_in[5];
  const float* vw    = (const float*)d_in[6];
  const float* vb    = (const float*)d_in[7];

  const int smem_bytes = 65536;
  cudaFuncSetAttribute(gemm_mma_kernel, cudaFuncAttributeMaxDynamicSharedMemorySize,
                       smem_bytes);

  convert_w_kernel<<<(3 * C_ * C_) / 256, 256>>>(qw, kw, vw);
  convert_x_kernel<<<dim3(HW_ / 32, C_ / 32, 4), dim3(32, 8)>>>(blue, white);
  gemm_mma_kernel<<<dim3(HW_ / 128, C_ / 128, 3 * B_), 256, smem_bytes>>>(qb, kb, vb);
  attn_kernel<<<dim3(NH, C_ / 4, B_), dim3(NW, 4)>>>((float*)d_out);
}

// round 4
// speedup vs baseline: 2.1110x; 1.2544x over previous
#include <cuda_runtime.h>
#include <cuda_fp16.h>
#include <cstdint>

#define B_  2
#define C_  256
#define H_  128
#define W_  128
#define HW_ (H_ * W_)
#define NH  32
#define NW  32

// ---------------------------------------------------------------------------
// Static scratch (no runtime allocation allowed).
// ---------------------------------------------------------------------------
__device__ __align__(256) __half g_Wh[3][C_ * C_];          // fp16(W*64) hi, [O][K]
__device__ __align__(256) __half g_Wl[3][C_ * C_];          // fp16 residual
__device__ __align__(256) __half g_Xh[4][(size_t)HW_ * C_]; // fp16(X^T), [hw][c]
__device__ float g_QKV[3][(size_t)B_ * C_ * HW_];           // Q,K,V fp32 [b][c][hw]

// ---------------------------------------------------------------------------
// Helpers
// ---------------------------------------------------------------------------
__device__ __forceinline__ uint32_t smem_u32(const void* p) {
  uint32_t a;
  asm("{ .reg .u64 t; cvta.to.shared.u64 t, %1; cvt.u32.u64 %0, t; }" : "=r"(a) : "l"(p));
  return a;
}

#define CP_ASYNC16(s, g) \
  asm volatile("cp.async.cg.shared.global [%0], [%1], 16;" :: "r"(s), "l"(g))
#define CP_COMMIT() asm volatile("cp.async.commit_group;" ::: "memory")
#define CP_WAIT0()  asm volatile("cp.async.wait_group 0;" ::: "memory")
#define CP_WAIT1()  asm volatile("cp.async.wait_group 1;" ::: "memory")

__device__ __forceinline__ void ldsm_x4(uint32_t* r, uint32_t addr) {
  asm volatile("ldmatrix.sync.aligned.m8n8.x4.shared.b16 {%0,%1,%2,%3}, [%4];"
               : "=r"(r[0]), "=r"(r[1]), "=r"(r[2]), "=r"(r[3]) : "r"(addr));
}

__device__ __forceinline__ void mma_f16(float* c, const uint32_t* a, const uint32_t* b) {
  asm volatile(
      "mma.sync.aligned.m16n8k16.row.col.f32.f16.f16.f32 "
      "{%0,%1,%2,%3}, {%4,%5,%6,%7}, {%8,%9}, {%0,%1,%2,%3};"
      : "+f"(c[0]), "+f"(c[1]), "+f"(c[2]), "+f"(c[3])
      : "r"(a[0]), "r"(a[1]), "r"(a[2]), "r"(a[3]), "r"(b[0]), "r"(b[1]));
}

// smem tile: 128 rows x 32 fp16 (64B rows, 4 x 16B chunks, XOR swizzle)
__device__ __forceinline__ uint32_t soff(int r, int c) {
  return (uint32_t)(r * 64 + ((c ^ ((r >> 1) & 3)) << 4));
}

// ---------------------------------------------------------------------------
// Kernel 0a: split weights (scaled by 2^6) into fp16 hi/lo.
// ---------------------------------------------------------------------------
__global__ void __launch_bounds__(256) convert_w_kernel(
    const float* __restrict__ qw, const float* __restrict__ kw,
    const float* __restrict__ vw) {
  int idx = blockIdx.x * 256 + threadIdx.x;
  int p = idx >> 16;
  int r = idx & 0xFFFF;
  const float* w = (p == 0) ? qw : (p == 1) ? kw : vw;
  float x = w[r] * 64.f;
  __half hi = __float2half_rn(x);
  g_Wh[p][r] = hi;
  g_Wl[p][r] = __float2half_rn(x - __half2float(hi));
}

// ---------------------------------------------------------------------------
// Kernel 0b: transpose X [c][hw] -> [hw][c] into fp16.
// ---------------------------------------------------------------------------
__global__ void __launch_bounds__(256) convert_x_kernel(
    const float* __restrict__ blue, const float* __restrict__ white) {
  __shared__ float t[32][33];
  const int hw0 = blockIdx.x * 32;
  const int c0 = blockIdx.y * 32;
  const int slab = blockIdx.z;
  const float* src = (slab < 2) ? blue + (size_t)slab * C_ * HW_
                                : white + (size_t)(slab - 2) * C_ * HW_;
  const int tx = threadIdx.x, ty = threadIdx.y;
#pragma unroll
  for (int it = 0; it < 4; it++) {
    int c = it * 8 + ty;
    t[c][tx] = src[(size_t)(c0 + c) * HW_ + hw0 + tx];
  }
  __syncthreads();
  const int tid = ty * 32 + tx;
  const int cp = tid & 15;
  const int hy = tid >> 4;
  __half* Xh = g_Xh[slab];
#pragma unroll
  for (int it = 0; it < 2; it++) {
    int hw = it * 16 + hy;
    float a = t[cp * 2][hw];
    float b = t[cp * 2 + 1][hw];
    __half2 vh;
    vh.x = __float2half_rn(a);
    vh.y = __float2half_rn(b);
    *(__half2*)(Xh + (size_t)(hw0 + hw) * C_ + c0 + cp * 2) = vh;
  }
}

// ---------------------------------------------------------------------------
// Kernel 1: fp16 2-pass GEMM via mma.sync (HMMA).
// Out[p][b][m][n] = (sum_k (Wh+Wl)[m][k] * X^T[n][k]) * 2^-6 + bias[m]
// CTA: 128(m) x 128(n), BK=32, 8 warps (2x4), warp 64x32, cp.async pipeline.
// ---------------------------------------------------------------------------
__global__ void __launch_bounds__(256, 1) gemm_mma_kernel(
    const float* __restrict__ qb, const float* __restrict__ kb,
    const float* __restrict__ vb) {
  extern __shared__ char sm[];
  const uint32_t sbase = smem_u32(sm);

  const int tid = threadIdx.x;
  const int lane = tid & 31;
  const int wid = tid >> 5;
  const int wm = wid >> 2;          // 0..1
  const int wn = wid & 3;           // 0..3

  const int z = blockIdx.z;         // 0..5
  const int p = z >> 1;
  const int b = z & 1;
  const int m0 = blockIdx.y * 128;
  const int n0 = blockIdx.x * 128;
  const int slab = (p == 0) ? b : 2 + b;

  const __half* __restrict__ gAh = g_Wh[p] + m0 * C_;
  const __half* __restrict__ gAl = g_Wl[p] + m0 * C_;
  const __half* __restrict__ gBh = g_Xh[slab] + (size_t)n0 * C_;

  // buffer layout: [Ahi 8K][Alo 8K][Bhi 8K], x2 buffers (24KB each)
  const int stg_r = tid >> 2;           // rows this thread stages (and +64)
  const int stg_c = tid & 3;

  float acc[4][4][4];
#pragma unroll
  for (int mt = 0; mt < 4; mt++)
#pragma unroll
    for (int nt = 0; nt < 4; nt++)
#pragma unroll
      for (int e = 0; e < 4; e++) acc[mt][nt][e] = 0.f;

#define ISSUE_STAGE(ks, buf)                                                     \
  {                                                                              \
    const int k0 = (ks) * 32;                                                    \
    _Pragma("unroll")                                                            \
    for (int it = 0; it < 2; it++) {                                             \
      int r = stg_r + it * 64;                                                   \
      uint32_t so = sbase + (buf) * 24576 + soff(r, stg_c);                      \
      CP_ASYNC16(so,         gAh + r * C_ + k0 + stg_c * 8);                     \
      CP_ASYNC16(so + 8192,  gAl + r * C_ + k0 + stg_c * 8);                     \
      CP_ASYNC16(so + 16384, gBh + (size_t)r * C_ + k0 + stg_c * 8);             \
    }                                                                            \
    CP_COMMIT();                                                                 \
  }

  ISSUE_STAGE(0, 0);

  for (int ks = 0; ks < 8; ks++) {
    const int buf = ks & 1;
    if (ks + 1 < 8) {
      ISSUE_STAGE(ks + 1, buf ^ 1);
      CP_WAIT1();
    } else {
      CP_WAIT0();
    }
    __syncthreads();

    const uint32_t Ab = sbase + buf * 24576;
    const uint32_t Bb = Ab + 16384;

#pragma unroll
    for (int kc = 0; kc < 2; kc++) {
      uint32_t ah[4][4], al[4][4], bh[2][4];
      const int arow = wm * 64 + (lane & 15);
      const int achunk = kc * 2 + (lane >> 4);
#pragma unroll
      for (int mt = 0; mt < 4; mt++) {
        int rr = arow + mt * 16;
        uint32_t ad = Ab + soff(rr, achunk);
        ldsm_x4(ah[mt], ad);
        ldsm_x4(al[mt], ad + 8192);
      }
      const int nrow = wn * 32 + ((lane >> 4) << 3) + (lane & 7);
      const int bchunk = kc * 2 + ((lane >> 3) & 1);
#pragma unroll
      for (int bt = 0; bt < 2; bt++) {
        int rr = nrow + bt * 16;
        ldsm_x4(bh[bt], Bb + soff(rr, bchunk));
      }
#pragma unroll
      for (int mt = 0; mt < 4; mt++) {
#pragma unroll
        for (int nt = 0; nt < 4; nt++) {
          const uint32_t* bhp = &bh[nt >> 1][(nt & 1) * 2];
          mma_f16(acc[mt][nt], ah[mt], bhp);
          mma_f16(acc[mt][nt], al[mt], bhp);
        }
      }
    }
    __syncthreads();
  }

  // ---- epilogue: unscale (2^-6) + bias + direct STG ----
  const float* __restrict__ biasp = (p == 0) ? qb : (p == 1) ? kb : vb;
  float* __restrict__ Out = g_QKV[p] + (size_t)b * C_ * HW_;
  const int mrow_base = m0 + wm * 64 + (lane >> 2);
  const int ncol_base = n0 + wn * 32 + (lane & 3) * 2;
  const float s = 0.015625f;  // 2^-6

#pragma unroll
  for (int mt = 0; mt < 4; mt++) {
    int mr = mrow_base + mt * 16;
    float bi0 = __ldg(biasp + mr);
    float bi1 = __ldg(biasp + mr + 8);
#pragma unroll
    for (int nt = 0; nt < 4; nt++) {
      int nc = ncol_base + nt * 8;
      float2 v0 = make_float2(fmaf(acc[mt][nt][0], s, bi0), fmaf(acc[mt][nt][1], s, bi0));
      float2 v1 = make_float2(fmaf(acc[mt][nt][2], s, bi1), fmaf(acc[mt][nt][3], s, bi1));
      *(float2*)(Out + (size_t)mr * HW_ + nc)       = v0;
      *(float2*)(Out + (size_t)(mr + 8) * HW_ + nc) = v1;
    }
  }
}

// ---------------------------------------------------------------------------
// Kernel 2: per-channel 3x3-neighbor token attention (unchanged).
// ---------------------------------------------------------------------------
__global__ void __launch_bounds__(128) attn_kernel(float* __restrict__ out) {
  const int j = threadIdx.x;
  const int i = blockIdx.x;
  const int c = blockIdx.y * 4 + threadIdx.y;
  const int b = blockIdx.z;

  const size_t base = ((size_t)b * C_ + c) * HW_;
  const float* __restrict__ Qp = g_QKV[0] + base;
  const float* __restrict__ Kp = g_QKV[1] + base;
  const float* __restrict__ Vp = g_QKV[2] + base;

  const int y0 = i * 4;
  const int x0 = j * 4;

  float4 q0 = *(const float4*)(Qp + (y0 + 0) * W_ + x0);
  float4 q1 = *(const float4*)(Qp + (y0 + 1) * W_ + x0);
  float4 q2 = *(const float4*)(Qp + (y0 + 2) * W_ + x0);
  float4 q3 = *(const float4*)(Qp + (y0 + 3) * W_ + x0);

  float lg[9];
  float mx = -1e30f;
#pragma unroll
  for (int n = 0; n < 9; n++) {
    const int ii = i + n / 3 - 1;
    const int jj = j + n % 3 - 1;
    float d = -1e30f;
    if ((unsigned)ii < (unsigned)NH && (unsigned)jj < (unsigned)NW) {
      const float* kp = Kp + (ii * 4) * W_ + jj * 4;
      float4 k0 = *(const float4*)(kp);
      float4 k1 = *(const float4*)(kp + W_);
      float4 k2 = *(const float4*)(kp + 2 * W_);
      float4 k3 = *(const float4*)(kp + 3 * W_);
      d  = q0.x * k0.x + q0.y * k0.y + q0.z * k0.z + q0.w * k0.w;
      d += q1.x * k1.x + q1.y * k1.y + q1.z * k1.z + q1.w * k1.w;
      d += q2.x * k2.x + q2.y * k2.y + q2.z * k2.z + q2.w * k2.w;
      d += q3.x * k3.x + q3.y * k3.y + q3.z * k3.z + q3.w * k3.w;
      d *= 0.25f;
    }
    lg[n] = d;
    mx = fmaxf(mx, d);
  }

  float wn[9];
  float wsum = 0.f;
#pragma unroll
  for (int n = 0; n < 9; n++) {
    float e = __expf(lg[n] - mx);
    wn[n] = e;
    wsum += e;
  }
  const float inv = 1.f / wsum;

  float4 o0 = {0, 0, 0, 0}, o1 = {0, 0, 0, 0}, o2 = {0, 0, 0, 0}, o3 = {0, 0, 0, 0};
#pragma unroll
  for (int n = 0; n < 9; n++) {
    const int ii = i + n / 3 - 1;
    const int jj = j + n % 3 - 1;
    if ((unsigned)ii < (unsigned)NH && (unsigned)jj < (unsigned)NW) {
      const float a = wn[n] * inv;
      const float* vp = Vp + (ii * 4) * W_ + jj * 4;
      float4 v0 = *(const float4*)(vp);
      float4 v1 = *(const float4*)(vp + W_);
      float4 v2 = *(const float4*)(vp + 2 * W_);
      float4 v3 = *(const float4*)(vp + 3 * W_);
      o0.x = fmaf(a, v0.x, o0.x); o0.y = fmaf(a, v0.y, o0.y);
      o0.z = fmaf(a, v0.z, o0.z); o0.w = fmaf(a, v0.w, o0.w);
      o1.x = fmaf(a, v1.x, o1.x); o1.y = fmaf(a, v1.y, o1.y);
      o1.z = fmaf(a, v1.z, o1.z); o1.w = fmaf(a, v1.w, o1.w);
      o2.x = fmaf(a, v2.x, o2.x); o2.y = fmaf(a, v2.y, o2.y);
      o2.z = fmaf(a, v2.z, o2.z); o2.w = fmaf(a, v2.w, o2.w);
      o3.x = fmaf(a, v3.x, o3.x); o3.y = fmaf(a, v3.y, o3.y);
      o3.z = fmaf(a, v3.z, o3.z); o3.w = fmaf(a, v3.w, o3.w);
    }
  }

  float* op = out + base + (size_t)y0 * W_ + x0;
  *(float4*)(op)          = o0;
  *(float4*)(op + W_)     = o1;
  *(float4*)(op + 2 * W_) = o2;
  *(float4*)(op + 3 * W_) = o3;
}

// ---------------------------------------------------------------------------
extern "C" void kernel_launch(void* const* d_in, const int* in_sizes, int n_in,
                              void* d_out, int out_size) {
  const float* blue  = (const float*)d_in[0];
  const float* white = (const float*)d_in[1];
  const float* qw    = (const float*)d_in[2];
  const float* qb    = (const float*)d_in[3];
  const float* kw    = (const float*)d_in[4];
  const float* kb    = (const float*)d_in[5];
  const float* vw    = (const float*)d_in[6];
  const float* vb    = (const float*)d_in[7];

  const int smem_bytes = 49152;
  cudaFuncSetAttribute(gemm_mma_kernel, cudaFuncAttributeMaxDynamicSharedMemorySize,
                       smem_bytes);

  convert_w_kernel<<<(3 * C_ * C_) / 256, 256>>>(qw, kw, vw);
  convert_x_kernel<<<dim3(HW_ / 32, C_ / 32, 4), dim3(32, 8)>>>(blue, white);
  gemm_mma_kernel<<<dim3(HW_ / 128, C_ / 128, 3 * B_), 256, smem_bytes>>>(qb, kb, vb);
  attn_kernel<<<dim3(NH, C_ / 4, B_), dim3(NW, 4)>>>((float*)d_out);
}

// round 5
// speedup vs baseline: 3.2437x; 1.5366x over previous
#include <cuda_runtime.h>
#include <cuda_fp16.h>
#include <cstdint>

#define B_  2
#define C_  256
#define H_  128
#define W_  128
#define HW_ (H_ * W_)
#define NH  32
#define NW  32

// ---------------------------------------------------------------------------
// Static scratch (no runtime allocation allowed).
// ---------------------------------------------------------------------------
__device__ __align__(256) __half g_Wh[3][C_ * C_];          // fp16(W), [O][K]
__device__ __align__(256) __half g_Xh[4][(size_t)HW_ * C_]; // fp16(X^T), [hw][c]
__device__ __align__(256) __half g_QK[2][(size_t)B_ * C_ * HW_]; // Q,K fp16 [b][c][hw]
__device__ float g_V[(size_t)B_ * C_ * HW_];                // V fp32 [b][c][hw]

// ---------------------------------------------------------------------------
// Helpers
// ---------------------------------------------------------------------------
__device__ __forceinline__ uint32_t smem_u32(const void* p) {
  uint32_t a;
  asm("{ .reg .u64 t; cvta.to.shared.u64 t, %1; cvt.u32.u64 %0, t; }" : "=r"(a) : "l"(p));
  return a;
}

#define CP_ASYNC16(s, g) \
  asm volatile("cp.async.cg.shared.global [%0], [%1], 16;" :: "r"(s), "l"(g))
#define CP_COMMIT() asm volatile("cp.async.commit_group;" ::: "memory")
#define CP_WAIT0()  asm volatile("cp.async.wait_group 0;" ::: "memory")
#define CP_WAIT1()  asm volatile("cp.async.wait_group 1;" ::: "memory")

__device__ __forceinline__ void ldsm_x4(uint32_t* r, uint32_t addr) {
  asm volatile("ldmatrix.sync.aligned.m8n8.x4.shared.b16 {%0,%1,%2,%3}, [%4];"
               : "=r"(r[0]), "=r"(r[1]), "=r"(r[2]), "=r"(r[3]) : "r"(addr));
}

__device__ __forceinline__ void mma_f16(float* c, const uint32_t* a, const uint32_t* b) {
  asm volatile(
      "mma.sync.aligned.m16n8k16.row.col.f32.f16.f16.f32 "
      "{%0,%1,%2,%3}, {%4,%5,%6,%7}, {%8,%9}, {%0,%1,%2,%3};"
      : "+f"(c[0]), "+f"(c[1]), "+f"(c[2]), "+f"(c[3])
      : "r"(a[0]), "r"(a[1]), "r"(a[2]), "r"(a[3]), "r"(b[0]), "r"(b[1]));
}

// smem tile: 128 rows x 32 fp16 (64B rows, 4 x 16B chunks, XOR swizzle)
__device__ __forceinline__ uint32_t soff(int r, int c) {
  return (uint32_t)(r * 64 + ((c ^ ((r >> 1) & 3)) << 4));
}

// load 4 consecutive halves as float4
__device__ __forceinline__ float4 ld_h4(const __half* p) {
  uint2 u = *(const uint2*)p;
  __half2 h0 = *(__half2*)&u.x;
  __half2 h1 = *(__half2*)&u.y;
  float2 f0 = __half22float2(h0);
  float2 f1 = __half22float2(h1);
  return make_float4(f0.x, f0.y, f1.x, f1.y);
}

// ---------------------------------------------------------------------------
// Kernel 0a: weights -> fp16.
// ---------------------------------------------------------------------------
__global__ void __launch_bounds__(256) convert_w_kernel(
    const float* __restrict__ qw, const float* __restrict__ kw,
    const float* __restrict__ vw) {
  int idx = blockIdx.x * 256 + threadIdx.x;
  int p = idx >> 16;
  int r = idx & 0xFFFF;
  const float* w = (p == 0) ? qw : (p == 1) ? kw : vw;
  g_Wh[p][r] = __float2half_rn(w[r]);
}

// ---------------------------------------------------------------------------
// Kernel 0b: transpose X [c][hw] -> [hw][c] into fp16.
// ---------------------------------------------------------------------------
__global__ void __launch_bounds__(256) convert_x_kernel(
    const float* __restrict__ blue, const float* __restrict__ white) {
  __shared__ float t[32][33];
  const int hw0 = blockIdx.x * 32;
  const int c0 = blockIdx.y * 32;
  const int slab = blockIdx.z;
  const float* src = (slab < 2) ? blue + (size_t)slab * C_ * HW_
                                : white + (size_t)(slab - 2) * C_ * HW_;
  const int tx = threadIdx.x, ty = threadIdx.y;
#pragma unroll
  for (int it = 0; it < 4; it++) {
    int c = it * 8 + ty;
    t[c][tx] = src[(size_t)(c0 + c) * HW_ + hw0 + tx];
  }
  __syncthreads();
  const int tid = ty * 32 + tx;
  const int cp = tid & 15;
  const int hy = tid >> 4;
  __half* Xh = g_Xh[slab];
#pragma unroll
  for (int it = 0; it < 2; it++) {
    int hw = it * 16 + hy;
    __half2 vh;
    vh.x = __float2half_rn(t[cp * 2][hw]);
    vh.y = __float2half_rn(t[cp * 2 + 1][hw]);
    *(__half2*)(Xh + (size_t)(hw0 + hw) * C_ + c0 + cp * 2) = vh;
  }
}

// ---------------------------------------------------------------------------
// Kernel 1: single-pass fp16 GEMM via mma.sync (HMMA).
// Out[p][b][m][n] = sum_k W[m][k] * X^T[n][k] + bias[m]
// CTA: 128(m) x 128(n), BK=32, 8 warps (2x4), warp 64x32, cp.async pipeline.
// Q,K written fp16; V written fp32.
// ---------------------------------------------------------------------------
__global__ void __launch_bounds__(256, 2) gemm_mma_kernel(
    const float* __restrict__ qb, const float* __restrict__ kb,
    const float* __restrict__ vb) {
  extern __shared__ char sm[];
  const uint32_t sbase = smem_u32(sm);

  const int tid = threadIdx.x;
  const int lane = tid & 31;
  const int wid = tid >> 5;
  const int wm = wid >> 2;          // 0..1
  const int wn = wid & 3;           // 0..3

  const int z = blockIdx.z;         // 0..5
  const int p = z >> 1;
  const int b = z & 1;
  const int m0 = blockIdx.y * 128;
  const int n0 = blockIdx.x * 128;
  const int slab = (p == 0) ? b : 2 + b;

  const __half* __restrict__ gA = g_Wh[p] + m0 * C_;
  const __half* __restrict__ gB = g_Xh[slab] + (size_t)n0 * C_;

  // buffer layout: [A 8K][B 8K], x2 buffers (16KB each)
  const int stg_r = tid >> 2;           // rows this thread stages (and +64)
  const int stg_c = tid & 3;

  float acc[4][4][4];
#pragma unroll
  for (int mt = 0; mt < 4; mt++)
#pragma unroll
    for (int nt = 0; nt < 4; nt++)
#pragma unroll
      for (int e = 0; e < 4; e++) acc[mt][nt][e] = 0.f;

#define ISSUE_STAGE(ks, buf)                                                     \
  {                                                                              \
    const int k0 = (ks) * 32;                                                    \
    _Pragma("unroll")                                                            \
    for (int it = 0; it < 2; it++) {                                             \
      int r = stg_r + it * 64;                                                   \
      uint32_t so = sbase + (buf) * 16384 + soff(r, stg_c);                      \
      CP_ASYNC16(so,        gA + r * C_ + k0 + stg_c * 8);                       \
      CP_ASYNC16(so + 8192, gB + (size_t)r * C_ + k0 + stg_c * 8);               \
    }                                                                            \
    CP_COMMIT();                                                                 \
  }

  ISSUE_STAGE(0, 0);

  for (int ks = 0; ks < 8; ks++) {
    const int buf = ks & 1;
    if (ks + 1 < 8) {
      ISSUE_STAGE(ks + 1, buf ^ 1);
      CP_WAIT1();
    } else {
      CP_WAIT0();
    }
    __syncthreads();

    const uint32_t Ab = sbase + buf * 16384;
    const uint32_t Bb = Ab + 8192;

#pragma unroll
    for (int kc = 0; kc < 2; kc++) {
      uint32_t ah[4][4], bh[2][4];
      const int arow = wm * 64 + (lane & 15);
      const int achunk = kc * 2 + (lane >> 4);
#pragma unroll
      for (int mt = 0; mt < 4; mt++) {
        int rr = arow + mt * 16;
        ldsm_x4(ah[mt], Ab + soff(rr, achunk));
      }
      const int nrow = wn * 32 + ((lane >> 4) << 3) + (lane & 7);
      const int bchunk = kc * 2 + ((lane >> 3) & 1);
#pragma unroll
      for (int bt = 0; bt < 2; bt++) {
        int rr = nrow + bt * 16;
        ldsm_x4(bh[bt], Bb + soff(rr, bchunk));
      }
#pragma unroll
      for (int mt = 0; mt < 4; mt++) {
#pragma unroll
        for (int nt = 0; nt < 4; nt++) {
          mma_f16(acc[mt][nt], ah[mt], &bh[nt >> 1][(nt & 1) * 2]);
        }
      }
    }
    __syncthreads();
  }

  // ---- epilogue: bias + store (fp16 for Q/K, fp32 for V) ----
  const float* __restrict__ biasp = (p == 0) ? qb : (p == 1) ? kb : vb;
  const int mrow_base = m0 + wm * 64 + (lane >> 2);
  const int ncol_base = n0 + wn * 32 + (lane & 3) * 2;

  if (p < 2) {
    __half* __restrict__ Out = g_QK[p] + (size_t)b * C_ * HW_;
#pragma unroll
    for (int mt = 0; mt < 4; mt++) {
      int mr = mrow_base + mt * 16;
      float bi0 = __ldg(biasp + mr);
      float bi1 = __ldg(biasp + mr + 8);
#pragma unroll
      for (int nt = 0; nt < 4; nt++) {
        int nc = ncol_base + nt * 8;
        *(__half2*)(Out + (size_t)mr * HW_ + nc) =
            __floats2half2_rn(acc[mt][nt][0] + bi0, acc[mt][nt][1] + bi0);
        *(__half2*)(Out + (size_t)(mr + 8) * HW_ + nc) =
            __floats2half2_rn(acc[mt][nt][2] + bi1, acc[mt][nt][3] + bi1);
      }
    }
  } else {
    float* __restrict__ Out = g_V + (size_t)b * C_ * HW_;
#pragma unroll
    for (int mt = 0; mt < 4; mt++) {
      int mr = mrow_base + mt * 16;
      float bi0 = __ldg(biasp + mr);
      float bi1 = __ldg(biasp + mr + 8);
#pragma unroll
      for (int nt = 0; nt < 4; nt++) {
        int nc = ncol_base + nt * 8;
        float2 v0 = make_float2(acc[mt][nt][0] + bi0, acc[mt][nt][1] + bi0);
        float2 v1 = make_float2(acc[mt][nt][2] + bi1, acc[mt][nt][3] + bi1);
        *(float2*)(Out + (size_t)mr * HW_ + nc)       = v0;
        *(float2*)(Out + (size_t)(mr + 8) * HW_ + nc) = v1;
      }
    }
  }
}

// ---------------------------------------------------------------------------
// Kernel 2: per-channel 3x3-neighbor token attention. Q,K fp16; V fp32.
// ---------------------------------------------------------------------------
__global__ void __launch_bounds__(128) attn_kernel(float* __restrict__ out) {
  const int j = threadIdx.x;
  const int i = blockIdx.x;
  const int c = blockIdx.y * 4 + threadIdx.y;
  const int b = blockIdx.z;

  const size_t base = ((size_t)b * C_ + c) * HW_;
  const __half* __restrict__ Qp = g_QK[0] + base;
  const __half* __restrict__ Kp = g_QK[1] + base;
  const float* __restrict__ Vp = g_V + base;

  const int y0 = i * 4;
  const int x0 = j * 4;

  float4 q0 = ld_h4(Qp + (y0 + 0) * W_ + x0);
  float4 q1 = ld_h4(Qp + (y0 + 1) * W_ + x0);
  float4 q2 = ld_h4(Qp + (y0 + 2) * W_ + x0);
  float4 q3 = ld_h4(Qp + (y0 + 3) * W_ + x0);

  float lg[9];
  float mx = -1e30f;
#pragma unroll
  for (int n = 0; n < 9; n++) {
    const int ii = i + n / 3 - 1;
    const int jj = j + n % 3 - 1;
    float d = -1e30f;
    if ((unsigned)ii < (unsigned)NH && (unsigned)jj < (unsigned)NW) {
      const __half* kp = Kp + (ii * 4) * W_ + jj * 4;
      float4 k0 = ld_h4(kp);
      float4 k1 = ld_h4(kp + W_);
      float4 k2 = ld_h4(kp + 2 * W_);
      float4 k3 = ld_h4(kp + 3 * W_);
      d  = q0.x * k0.x + q0.y * k0.y + q0.z * k0.z + q0.w * k0.w;
      d += q1.x * k1.x + q1.y * k1.y + q1.z * k1.z + q1.w * k1.w;
      d += q2.x * k2.x + q2.y * k2.y + q2.z * k2.z + q2.w * k2.w;
      d += q3.x * k3.x + q3.y * k3.y + q3.z * k3.z + q3.w * k3.w;
      d *= 0.25f;
    }
    lg[n] = d;
    mx = fmaxf(mx, d);
  }

  float wn[9];
  float wsum = 0.f;
#pragma unroll
  for (int n = 0; n < 9; n++) {
    float e = __expf(lg[n] - mx);
    wn[n] = e;
    wsum += e;
  }
  const float inv = 1.f / wsum;

  float4 o0 = {0, 0, 0, 0}, o1 = {0, 0, 0, 0}, o2 = {0, 0, 0, 0}, o3 = {0, 0, 0, 0};
#pragma unroll
  for (int n = 0; n < 9; n++) {
    const int ii = i + n / 3 - 1;
    const int jj = j + n % 3 - 1;
    if ((unsigned)ii < (unsigned)NH && (unsigned)jj < (unsigned)NW) {
      const float a = wn[n] * inv;
      const float* vp = Vp + (ii * 4) * W_ + jj * 4;
      float4 v0 = *(const float4*)(vp);
      float4 v1 = *(const float4*)(vp + W_);
      float4 v2 = *(const float4*)(vp + 2 * W_);
      float4 v3 = *(const float4*)(vp + 3 * W_);
      o0.x = fmaf(a, v0.x, o0.x); o0.y = fmaf(a, v0.y, o0.y);
      o0.z = fmaf(a, v0.z, o0.z); o0.w = fmaf(a, v0.w, o0.w);
      o1.x = fmaf(a, v1.x, o1.x); o1.y = fmaf(a, v1.y, o1.y);
      o1.z = fmaf(a, v1.z, o1.z); o1.w = fmaf(a, v1.w, o1.w);
      o2.x = fmaf(a, v2.x, o2.x); o2.y = fmaf(a, v2.y, o2.y);
      o2.z = fmaf(a, v2.z, o2.z); o2.w = fmaf(a, v2.w, o2.w);
      o3.x = fmaf(a, v3.x, o3.x); o3.y = fmaf(a, v3.y, o3.y);
      o3.z = fmaf(a, v3.z, o3.z); o3.w = fmaf(a, v3.w, o3.w);
    }
  }

  float* op = out + base + (size_t)y0 * W_ + x0;
  *(float4*)(op)          = o0;
  *(float4*)(op + W_)     = o1;
  *(float4*)(op + 2 * W_) = o2;
  *(float4*)(op + 3 * W_) = o3;
}

// ---------------------------------------------------------------------------
extern "C" void kernel_launch(void* const* d_in, const int* in_sizes, int n_in,
                              void* d_out, int out_size) {
  const float* blue  = (const float*)d_in[0];
  const float* white = (const float*)d_in[1];
  const float* qw    = (const float*)d_in[2];
  const float* qb    = (const float*)d_in[3];
  const float* kw    = (const float*)d_in[4];
  const float* kb    = (const float*)d_in[5];
  const float* vw    = (const float*)d_in[6];
  const float* vb    = (const float*)d_in[7];

  const int smem_bytes = 32768;
  cudaFuncSetAttribute(gemm_mma_kernel, cudaFuncAttributeMaxDynamicSharedMemorySize,
                       smem_bytes);

  convert_w_kernel<<<(3 * C_ * C_) / 256, 256>>>(qw, kw, vw);
  convert_x_kernel<<<dim3(HW_ / 32, C_ / 32, 4), dim3(32, 8)>>>(blue, white);
  gemm_mma_kernel<<<dim3(HW_ / 128, C_ / 128, 3 * B_), 256, smem_bytes>>>(qb, kb, vb);
  attn_kernel<<<dim3(NH, C_ / 4, B_), dim3(NW, 4)>>>((float*)d_out);
}